// round 12
// baseline (speedup 1.0000x reference)
#include <cuda_runtime.h>

// ---------------------------------------------------------------------------
// GNNMLP fused kernel, round 11 = round 10 + shuffle-based neigh matmul.
//  * dup activation layout; 16B lds128 broadcasts feed two k-steps.
//  * weights: plain b64 derefs (LDS.64 smem / LDG.64 global) - clean codegen.
//  * NEW: neigh vector kept in registers; neigh@Wn uses __shfl_sync broadcast
//    instead of an smem NB round-trip: -136 L1 wavefronts/group (the binding
//    pipe at 88.7%), +4 SHFL +8 MOV per kh (idle pipes).
//  * conv: 2 groups/warp; MLP: 4-group ring; 16 warps; smem 200.7KB.
// ---------------------------------------------------------------------------

#define G_TOT   131072
#define THREADS 512
#define WARPS   16
#define RING    4

typedef unsigned long long ull;

// ---- packed f32x2 helpers --------------------------------------------------
__device__ __forceinline__ float2 upk(ull v) {
    float2 r; asm("mov.b64 {%0,%1}, %2;" : "=f"(r.x), "=f"(r.y) : "l"(v)); return r;
}
__device__ __forceinline__ ull pk1(float v) {
    ull r; asm("mov.b64 %0, {%1,%1};" : "=l"(r) : "f"(v)); return r;
}
__device__ __forceinline__ ull f2fma(ull a, ull b, ull c) {
    ull d; asm("fma.rn.f32x2 %0, %1, %2, %3;" : "=l"(d) : "l"(a), "l"(b), "l"(c));
    return d;
}
__device__ __forceinline__ ull f2add(ull a, ull b) {
    ull d; asm("add.rn.f32x2 %0, %1, %2;" : "=l"(d) : "l"(a), "l"(b)); return d;
}
__device__ __forceinline__ void lds128(ull& a, ull& b, unsigned addr) {
    asm volatile("ld.shared.v2.u64 {%0,%1}, [%2];" : "=l"(a), "=l"(b) : "r"(addr));
}
__device__ __forceinline__ void sts128(unsigned a, float x, float y, float z, float w) {
    asm volatile("st.shared.v4.f32 [%0], {%1,%2,%3,%4};"
                 :: "r"(a), "f"(x), "f"(y), "f"(z), "f"(w));
}

// ---- SMEM layout (float offsets) ------------------------------------------
#define OFF_WP1  0
#define OFF_WS1  4096
#define OFF_WP2  8192
#define OFF_WS2  12288
#define OFF_MISC 16384
//  MISC: +0 bp1 +64 b1 +128 bp2 +192 b2 +256 Mb1[128] +384 Mb2[128]
//        +512 Mb3[128] +640 MW4[2][64][2]=256 +896 Mb4[4]
#define OFF_WS_  17408
#define WARP_WS  2048   // OBS dup[12][128]=1536 | RES ring dup[4][128]=512
#define SMEM_FLOATS (OFF_WS_ + WARPS * WARP_WS)   // 50176
#define SMEM_BYTES  (SMEM_FLOATS * 4)             // 200704 < 232448

struct Params {
    const float *obs, *Wp1, *bp1, *Ws1, *Wn1, *b1;
    const float *Wp2, *bp2, *Ws2, *Wn2, *b2;
    const float *MW1, *Mb1, *MW2, *Mb2, *MW3, *Mb3, *MW4, *Mb4;
    float *out;
    int ch;          // groups per warp (multiple of RING)
};

extern __shared__ float smem[];

__device__ __forceinline__ void cp4(float* dst, const float* src, int n) {
    for (int i = threadIdx.x; i < (n >> 2); i += THREADS)
        ((float4*)dst)[i] = ((const float4*)src)[i];
}

// ---- one SAGE-pool conv, 2 groups (12 dup rows) ----------------------------
// ROWS (byte addr): dup [12][128 floats]; row r at +r*512B, k-pair kh at +kh*16B.
// Weights: smem ull* lane-strided, W[k] pair at index k*32. Lane owns cols {2l,2l+1}.
// Neigh matmul: register max values broadcast via __shfl_sync (no smem).
template<bool FIRST>
__device__ __forceinline__ void conv2g(unsigned ROWS, unsigned RESb,
                                       const ull* wp, const ull* ws,
                                       const ull* __restrict__ wn,
                                       const float* misc, int bP, int bB, int lane)
{
    ull aP[12], aS[12];
    ull bpv = *(const ull*)(misc + bP + 2 * lane);
    #pragma unroll
    for (int r = 0; r < 12; r++) { aP[r] = bpv; aS[r] = 0ull; }

    #pragma unroll 4
    for (int kh = 0; kh < 32; kh++) {
        ull wp0 = wp[(2 * kh) * 32];         // LDS.64 lane-strided
        ull wp1 = wp[(2 * kh + 1) * 32];
        ull ws0 = ws[(2 * kh) * 32];
        ull ws1 = ws[(2 * kh + 1) * 32];
        #pragma unroll
        for (int r = 0; r < 12; r++) {
            ull b0, b1;                       // (x_k,x_k),(x_k1,x_k1) 16B bc
            lds128(b0, b1, ROWS + r * 512 + kh * 16);
            aP[r] = f2fma(b1, wp1, f2fma(b0, wp0, aP[r]));
            aS[r] = f2fma(b1, ws1, f2fma(b0, ws0, aS[r]));
        }
    }

    // neigh = max over 6 agents of relu(p); relu folded via 0-init.
    // Lane l holds neigh cols {2l, 2l+1} for both groups in registers.
    float mx0 = 0.f, my0 = 0.f, mx1 = 0.f, my1 = 0.f;
    #pragma unroll
    for (int r = 0; r < 6; r++) {
        float2 p = upk(aP[r]);
        mx0 = fmaxf(mx0, p.x); my0 = fmaxf(my0, p.y);
    }
    #pragma unroll
    for (int r = 6; r < 12; r++) {
        float2 p = upk(aP[r]);
        mx1 = fmaxf(mx1, p.x); my1 = fmaxf(my1, p.y);
    }
    __syncwarp();   // all lanes' ROWS reads complete before epilogue overwrites

    // nn = neigh @ Wn; neigh[2kh]/[2kh+1] live in lane kh's (mx,my) regs.
    ull nn0 = 0ull, nn1 = 0ull;
    #pragma unroll 4
    for (int kh = 0; kh < 32; kh++) {
        ull w0 = wn[(2 * kh) * 32];           // LDG.64 lane-strided (L2/L1)
        ull w1 = wn[(2 * kh + 1) * 32];
        float a = __shfl_sync(0xffffffffu, mx0, kh);
        float b = __shfl_sync(0xffffffffu, my0, kh);
        float c = __shfl_sync(0xffffffffu, mx1, kh);
        float d = __shfl_sync(0xffffffffu, my1, kh);
        nn0 = f2fma(pk1(b), w1, f2fma(pk1(a), w0, nn0));
        nn1 = f2fma(pk1(d), w1, f2fma(pk1(c), w0, nn1));
    }
    ull bbv = *(const ull*)(misc + bB + 2 * lane);
    float2 n0 = upk(f2add(nn0, bbv));
    float2 n1 = upk(f2add(nn1, bbv));

    if (FIRST) {
        #pragma unroll
        for (int r = 0; r < 12; r++) {
            float2 s = upk(aS[r]);
            float nx = (r < 6) ? n0.x : n1.x, ny = (r < 6) ? n0.y : n1.y;
            float v0 = tanhf(s.x + nx);
            float v1 = tanhf(s.y + ny);
            sts128(ROWS + r * 512 + lane * 16, v0, v0, v1, v1);
        }
    } else {
        #pragma unroll
        for (int g = 0; g < 2; g++) {
            ull t = aS[g * 6];
            #pragma unroll
            for (int r = g * 6 + 1; r < g * 6 + 6; r++) t = f2add(t, aS[r]);
            float2 s = upk(t);
            float v0 = s.x * (1.f / 6.f) + (g ? n1.x : n0.x);
            float v1 = s.y * (1.f / 6.f) + (g ? n1.y : n0.y);
            sts128(RESb + g * 512 + lane * 16, v0, v0, v1, v1);
        }
    }
    __syncwarp();
}

__global__ void __launch_bounds__(THREADS, 1) gnn_kernel(Params P)
{
    cp4(smem + OFF_WP1, P.Wp1, 4096);
    cp4(smem + OFF_WS1, P.Ws1, 4096);
    cp4(smem + OFF_WP2, P.Wp2, 4096);
    cp4(smem + OFF_WS2, P.Ws2, 4096);
    cp4(smem + OFF_MISC +   0, P.bp1, 64);
    cp4(smem + OFF_MISC +  64, P.b1,  64);
    cp4(smem + OFF_MISC + 128, P.bp2, 64);
    cp4(smem + OFF_MISC + 192, P.b2,  64);
    cp4(smem + OFF_MISC + 256, P.Mb1, 128);
    cp4(smem + OFF_MISC + 384, P.Mb2, 128);
    cp4(smem + OFF_MISC + 512, P.Mb3, 128);
    cp4(smem + OFF_MISC + 640, P.MW4, 256);
    cp4(smem + OFF_MISC + 896, P.Mb4, 4);
    __syncthreads();

    const int lane = threadIdx.x & 31;
    const int warp = threadIdx.x >> 5;
    const float* misc = smem + OFF_MISC;

    const unsigned sb  = (unsigned)__cvta_generic_to_shared(smem);
    const unsigned wsb = sb + (OFF_WS_ + warp * WARP_WS) * 4;
    const unsigned OBS = wsb;                 // dup [12][128fl] = 6144 B
    const unsigned XA0 = wsb;                 // alias: dup [4][128] (2048 B)
    const unsigned XA1 = wsb + 2048;          // alias
    const unsigned XB  = wsb + 4096;          // alias (OBS is 6144 B total)
    const unsigned RES = wsb + 6144;          // ring dup [4][128] = 2048 B

    const ull* sWP1 = (const ull*)(smem + OFF_WP1) + lane;
    const ull* sWS1 = (const ull*)(smem + OFF_WS1) + lane;
    const ull* sWP2 = (const ull*)(smem + OFF_WP2) + lane;
    const ull* sWS2 = (const ull*)(smem + OFF_WS2) + lane;
    const ull* gWN1 = (const ull*)P.Wn1 + lane;
    const ull* gWN2 = (const ull*)P.Wn2 + lane;

    const int wg   = blockIdx.x * WARPS + warp;
    const int base = wg * P.ch;
    const int iters = P.ch >> 1;

    for (int j = 0; j < iters; j++) {
        const int g0 = base + 2 * j, g1 = g0 + 1;

        // stage obs duplicated: float2 (a,b) -> (a,a,b,b); group1 at +3072 B
        {
            const float2* s0 = (const float2*)(P.obs + (size_t)g0 * 384);
            const float2* s1 = (const float2*)(P.obs + (size_t)g1 * 384);
            const float2 z = make_float2(0.f, 0.f);
            #pragma unroll
            for (int i = 0; i < 6; i++) {
                int m = lane + 32 * i;        // m = row*32 + kpair
                float2 a = (g0 < G_TOT) ? s0[m] : z;
                float2 b = (g1 < G_TOT) ? s1[m] : z;
                sts128(OBS + m * 16,        a.x, a.x, a.y, a.y);
                sts128(OBS + 3072 + m * 16, b.x, b.x, b.y, b.y);
            }
        }
        __syncwarp();

        const unsigned RESb = RES + (j & 1) * 1024;   // 2 groups per slot
        conv2g<true >(OBS, RESb, sWP1, sWS1, gWN1, misc,   0,  64, lane);
        conv2g<false>(OBS, RESb, sWP2, sWS2, gWN2, misc, 128, 192, lane);

        if (j & 1) {
            // ---- MLP on RING=4 groups ----
            const int gbase = base + 2 * (j - 1);

            // L1 fused over both types: RES -> XA0/XA1
            ull a0[4], a1[4];
            ull b10 = *(const ull*)(misc + 256 + 2 * lane);
            ull b11 = *(const ull*)(misc + 256 + 64 + 2 * lane);
            #pragma unroll
            for (int g = 0; g < 4; g++) { a0[g] = b10; a1[g] = b11; }
            {
                const ull* __restrict__ wA = (const ull*)P.MW1 + lane;
                const ull* __restrict__ wB = (const ull*)(P.MW1 + 4096) + lane;
                #pragma unroll 4
                for (int kh = 0; kh < 32; kh++) {
                    ull wA0 = wA[(2 * kh) * 32], wA1 = wA[(2 * kh + 1) * 32];
                    ull wB0 = wB[(2 * kh) * 32], wB1 = wB[(2 * kh + 1) * 32];
                    #pragma unroll
                    for (int g = 0; g < 4; g++) {
                        ull b0, b1;
                        lds128(b0, b1, RES + g * 512 + kh * 16);
                        a0[g] = f2fma(b1, wA1, f2fma(b0, wA0, a0[g]));
                        a1[g] = f2fma(b1, wB1, f2fma(b0, wB0, a1[g]));
                    }
                }
            }
            __syncwarp();      // RES reads done; XA0/XA1 alias OBS (dead)
            #pragma unroll
            for (int g = 0; g < 4; g++) {
                float2 v = upk(a0[g]);
                sts128(XA0 + g * 512 + lane * 16,
                       fmaxf(v.x, 0.f), fmaxf(v.x, 0.f),
                       fmaxf(v.y, 0.f), fmaxf(v.y, 0.f));
                v = upk(a1[g]);
                sts128(XA1 + g * 512 + lane * 16,
                       fmaxf(v.x, 0.f), fmaxf(v.x, 0.f),
                       fmaxf(v.y, 0.f), fmaxf(v.y, 0.f));
            }
            __syncwarp();

            float hA[4], hB[4];
            #pragma unroll
            for (int t = 0; t < 2; t++) {
                const unsigned XAt = t ? XA1 : XA0;

                // L2: XA_t -> XB
                ull a2[4];
                ull b2v = *(const ull*)(misc + 384 + t * 64 + 2 * lane);
                #pragma unroll
                for (int g = 0; g < 4; g++) a2[g] = b2v;
                {
                    const ull* __restrict__ w2 = (const ull*)(P.MW2 + t * 4096) + lane;
                    #pragma unroll 4
                    for (int kh = 0; kh < 32; kh++) {
                        ull w0 = w2[(2 * kh) * 32], w1 = w2[(2 * kh + 1) * 32];
                        #pragma unroll
                        for (int g = 0; g < 4; g++) {
                            ull b0, b1;
                            lds128(b0, b1, XAt + g * 512 + kh * 16);
                            a2[g] = f2fma(b1, w1, f2fma(b0, w0, a2[g]));
                        }
                    }
                }
                #pragma unroll
                for (int g = 0; g < 4; g++) {
                    float2 v = upk(a2[g]);
                    sts128(XB + g * 512 + lane * 16,
                           fmaxf(v.x, 0.f), fmaxf(v.x, 0.f),
                           fmaxf(v.y, 0.f), fmaxf(v.y, 0.f));
                }
                __syncwarp();

                // L3: XB -> regs; head directly from registers
                ull a3[4];
                ull b3v = *(const ull*)(misc + 512 + t * 64 + 2 * lane);
                #pragma unroll
                for (int g = 0; g < 4; g++) a3[g] = b3v;
                {
                    const ull* __restrict__ w3 = (const ull*)(P.MW3 + t * 4096) + lane;
                    #pragma unroll 4
                    for (int kh = 0; kh < 32; kh++) {
                        ull w0 = w3[(2 * kh) * 32], w1 = w3[(2 * kh + 1) * 32];
                        #pragma unroll
                        for (int g = 0; g < 4; g++) {
                            ull b0, b1;
                            lds128(b0, b1, XB + g * 512 + kh * 16);
                            a3[g] = f2fma(b1, w1, f2fma(b0, w0, a3[g]));
                        }
                    }
                }
                __syncwarp();  // XB reads done before t=1 overwrites

                float4 w4 = *(const float4*)(misc + 640 + t * 128 + 4 * lane);
                float b40 = misc[896 + t * 2], b41 = misc[896 + t * 2 + 1];
                #pragma unroll
                for (int g = 0; g < 4; g++) {
                    float2 v = upk(a3[g]);
                    float v0 = fmaxf(v.x, 0.f), v1 = fmaxf(v.y, 0.f);
                    float s0 = v0 * w4.x + v1 * w4.z;
                    float s1 = v0 * w4.y + v1 * w4.w;
                    #pragma unroll
                    for (int off = 16; off; off >>= 1) {
                        s0 += __shfl_xor_sync(0xffffffffu, s0, off);
                        s1 += __shfl_xor_sync(0xffffffffu, s1, off);
                    }
                    float r0 = tanhf(s0 + b40), r1 = tanhf(s1 + b41);
                    if (t == 0) { hA[g] = r0; hB[g] = r1; }
                    else {
                        int go = gbase + g;
                        if (go < G_TOT && lane < 3) {
                            float A = hA[g], B = hB[g];
                            float4 v4 = (lane < 2) ? make_float4(A, B, A, B)
                                                   : make_float4(A, B, r0, r1);
                            ((float4*)(P.out + (size_t)go * 12))[lane] = v4;
                        }
                    }
                }
            }
            __syncwarp();      // workspace reused by next conv iteration
        }
    }
}

extern "C" void kernel_launch(void* const* d_in, const int* in_sizes, int n_in,
                              void* d_out, int out_size)
{
    (void)in_sizes; (void)n_in; (void)out_size;
    Params P;
    P.obs = (const float*)d_in[0];
    P.Wp1 = (const float*)d_in[1];  P.bp1 = (const float*)d_in[2];
    P.Ws1 = (const float*)d_in[3];  P.Wn1 = (const float*)d_in[4];
    P.b1  = (const float*)d_in[5];
    P.Wp2 = (const float*)d_in[6];  P.bp2 = (const float*)d_in[7];
    P.Ws2 = (const float*)d_in[8];  P.Wn2 = (const float*)d_in[9];
    P.b2  = (const float*)d_in[10];
    P.MW1 = (const float*)d_in[11]; P.Mb1 = (const float*)d_in[12];
    P.MW2 = (const float*)d_in[13]; P.Mb2 = (const float*)d_in[14];
    P.MW3 = (const float*)d_in[15]; P.Mb3 = (const float*)d_in[16];
    P.MW4 = (const float*)d_in[17]; P.Mb4 = (const float*)d_in[18];
    P.out = (float*)d_out;

    int dev = 0, nsm = 148;
    cudaGetDevice(&dev);
    cudaDeviceGetAttribute(&nsm, cudaDevAttrMultiProcessorCount, dev);

    int nw = nsm * WARPS;
    int ch = ((G_TOT + nw * RING - 1) / (nw * RING)) * RING;
    P.ch = ch;

    cudaFuncSetAttribute(gnn_kernel, cudaFuncAttributeMaxDynamicSharedMemorySize,
                         SMEM_BYTES);
    gnn_kernel<<<nsm, THREADS, SMEM_BYTES>>>(P);
}

// round 14
// speedup vs baseline: 1.9049x; 1.9049x over previous
#include <cuda_runtime.h>
#include <cstdint>

// ---------------------------------------------------------------------------
// GNNMLP round 13: legacy mma.sync bf16 3-split tensor path (base sm_103 ISA;
// tcgen05 unavailable in this toolchain's PTX target).
//   * warp-private chunk = 16 groups (m16). All GEMMs [16,64]x[64,64] via
//     mma.sync.m16n8k16.f32.bf16.bf16.f32, 3-term split (aH*bH+aH*bL+aL*bH)
//     for ~1e-5 accuracy; fp32 accumulators.
//   * activations staged per warp in private smem as bf16 hi/lo [16][72]
//     (144B row stride, conflict-free ldmatrix); A-frags via ldmatrix.x4.
//   * weights pre-packed by prep kernel into exact B-fragment register order
//     in global memory -> plain coalesced LDG.64, L1-resident per phase.
//   * pooling/tanh/relu elementwise on D-fragments in registers; no CTA
//     barriers in the mainloop (warp-synchronous only).
// ---------------------------------------------------------------------------

#define G_TOT   131072
#define CHUNKS  8192          // G_TOT / 16
#define NW      12
#define THREADS 384

typedef unsigned long long ull;

// 12 matrices x 4096 u32 frags: [term(2)][s(4)][j(8)][lane(32)][reg(2)]
// m: 0 Wp1, 1 Ws1, 2 Wn1, 3 Wp2, 4 Ws2, 5 Wn2, 6 MW1t0, 7 MW1t1,
//    8 MW2t0, 9 MW2t1, 10 MW3t0, 11 MW3t1
__device__ uint32_t g_frag[12 * 4096];

// ---- helpers ---------------------------------------------------------------
__device__ __forceinline__ uint32_t smem_u32(const void* p) {
    uint32_t a;
    asm("{ .reg .u64 t; cvta.to.shared.u64 t, %1; cvt.u32.u64 %0, t; }"
        : "=r"(a) : "l"(p));
    return a;
}
__device__ __forceinline__ void sts32(uint32_t a, uint32_t v) {
    asm volatile("st.shared.b32 [%0], %1;" :: "r"(a), "r"(v));
}
__device__ __forceinline__ void ldmx4(uint32_t& r0, uint32_t& r1, uint32_t& r2,
                                      uint32_t& r3, uint32_t addr) {
    asm volatile("ldmatrix.sync.aligned.m8n8.x4.shared.b16 {%0,%1,%2,%3}, [%4];"
                 : "=r"(r0), "=r"(r1), "=r"(r2), "=r"(r3) : "r"(addr));
}
__device__ __forceinline__ void mma4(float* d, uint32_t a0, uint32_t a1,
                                     uint32_t a2, uint32_t a3,
                                     uint32_t b0, uint32_t b1) {
    asm volatile("mma.sync.aligned.m16n8k16.row.col.f32.bf16.bf16.f32 "
                 "{%0,%1,%2,%3},{%4,%5,%6,%7},{%8,%9},{%0,%1,%2,%3};"
                 : "+f"(d[0]), "+f"(d[1]), "+f"(d[2]), "+f"(d[3])
                 : "r"(a0), "r"(a1), "r"(a2), "r"(a3), "r"(b0), "r"(b1));
}
// split x,y into bf16 hi/lo pairs; store hi u32 at AH+off, lo at AL+off
__device__ __forceinline__ void split_store(uint32_t AH, uint32_t AL,
                                            uint32_t off, float x, float y) {
    unsigned short hx, hy, lx, ly;
    asm("cvt.rn.bf16.f32 %0, %1;" : "=h"(hx) : "f"(x));
    asm("cvt.rn.bf16.f32 %0, %1;" : "=h"(hy) : "f"(y));
    float rx = x - __uint_as_float((uint32_t)hx << 16);
    float ry = y - __uint_as_float((uint32_t)hy << 16);
    asm("cvt.rn.bf16.f32 %0, %1;" : "=h"(lx) : "f"(rx));
    asm("cvt.rn.bf16.f32 %0, %1;" : "=h"(ly) : "f"(ry));
    sts32(AH + off, (uint32_t)hx | ((uint32_t)hy << 16));
    sts32(AL + off, (uint32_t)lx | ((uint32_t)ly << 16));
}

// ---- prep kernel: weights -> B-fragment-ordered bf16 hi/lo images ----------
__global__ void prep_frag(const float* Wp1, const float* Ws1, const float* Wn1,
                          const float* Wp2, const float* Ws2, const float* Wn2,
                          const float* MW1, const float* MW2, const float* MW3)
{
    int j = blockIdx.x * blockDim.x + threadIdx.x;
    if (j >= 12 * 4096) return;
    int m = j >> 12, e = j & 4095;
    int term = e >> 11, s = (e >> 9) & 3, jt = (e >> 6) & 7;
    int lane = (e >> 1) & 31, reg = e & 1;
    const float* src;
    switch (m) {
        case 0: src = Wp1; break;  case 1: src = Ws1; break;
        case 2: src = Wn1; break;  case 3: src = Wp2; break;
        case 4: src = Ws2; break;  case 5: src = Wn2; break;
        case 6: src = MW1; break;  case 7: src = MW1 + 4096; break;
        case 8: src = MW2; break;  case 9: src = MW2 + 4096; break;
        case 10: src = MW3; break; default: src = MW3 + 4096; break;
    }
    int k0 = s * 16 + (lane & 3) * 2 + reg * 8;
    int n  = jt * 8 + (lane >> 2);
    float x0 = src[k0 * 64 + n], x1 = src[(k0 + 1) * 64 + n];
    unsigned short h0, h1;
    asm("cvt.rn.bf16.f32 %0, %1;" : "=h"(h0) : "f"(x0));
    asm("cvt.rn.bf16.f32 %0, %1;" : "=h"(h1) : "f"(x1));
    if (term == 1) {
        float r0 = x0 - __uint_as_float((uint32_t)h0 << 16);
        float r1 = x1 - __uint_as_float((uint32_t)h1 << 16);
        asm("cvt.rn.bf16.f32 %0, %1;" : "=h"(h0) : "f"(r0));
        asm("cvt.rn.bf16.f32 %0, %1;" : "=h"(h1) : "f"(r1));
    }
    g_frag[j] = (uint32_t)h0 | ((uint32_t)h1 << 16);
}

// ---- GEMM [16,64]x[64,64] with 3-split, acc[32] fp32 (D-frag layout) -------
__device__ __forceinline__ void gemm8(float* acc, uint32_t AH, uint32_t AL,
                                      const uint32_t* __restrict__ fb,
                                      int lane, bool zero)
{
    if (zero) {
        #pragma unroll
        for (int i = 0; i < 32; i++) acc[i] = 0.f;
    }
    #pragma unroll
    for (int s = 0; s < 4; s++) {
        uint32_t ad = (uint32_t)((lane & 15) * 144 + s * 32 + (lane >> 4) * 16);
        uint32_t aH0, aH1, aH2, aH3, aL0, aL1, aL2, aL3;
        ldmx4(aH0, aH1, aH2, aH3, AH + ad);
        ldmx4(aL0, aL1, aL2, aL3, AL + ad);
        #pragma unroll
        for (int jn = 0; jn < 8; jn++) {
            uint2 bh = *(const uint2*)(fb + s * 512 + jn * 64 + lane * 2);
            uint2 bl = *(const uint2*)(fb + 2048 + s * 512 + jn * 64 + lane * 2);
            mma4(acc + jn * 4, aH0, aH1, aH2, aH3, bh.x, bh.y);
            mma4(acc + jn * 4, aH0, aH1, aH2, aH3, bl.x, bl.y);
            mma4(acc + jn * 4, aL0, aL1, aL2, aL3, bh.x, bh.y);
        }
    }
}

// store D-layout regs v[32] into A tile (bf16 hi/lo)
__device__ __forceinline__ void stageD(uint32_t AH, uint32_t AL,
                                       const float* v, int lane)
{
    int r = lane >> 2, q = (lane & 3) * 2;
    #pragma unroll
    for (int j = 0; j < 8; j++) {
        uint32_t c = j * 8 + q;
        split_store(AH, AL, (uint32_t)((r * 72 + c) * 2),       v[j*4],   v[j*4+1]);
        split_store(AH, AL, (uint32_t)(((r + 8) * 72 + c) * 2), v[j*4+2], v[j*4+3]);
    }
}

// stage one agent's obs rows [16][64] into A tile
__device__ __forceinline__ void stage_obs(uint32_t AH, uint32_t AL,
                                          const float* __restrict__ src, int lane)
{
    int r = lane >> 1, f0 = (lane & 1) * 32;
    const float4* s4 = (const float4*)(src + (size_t)r * 384 + f0);
    uint32_t bo = (uint32_t)((r * 72 + f0) * 2);
    #pragma unroll
    for (int i = 0; i < 8; i++) {
        float4 v = s4[i];
        split_store(AH, AL, bo + i * 8,     v.x, v.y);
        split_store(AH, AL, bo + i * 8 + 4, v.z, v.w);
    }
}

struct Pm {
    const float *obs, *bp1, *b1, *bp2, *b2, *Mb1, *Mb2, *Mb3, *MW4, *Mb4;
    float* out;
};

extern __shared__ char smem[];
// smem: [0,4096) misc floats; warp w region at 4096 + w*9216:
//   AH0 +0, AL0 +2304, AH1 +4608, AL1 +6912   (tile = 16 rows x 144B)
#define SMEM_TOTAL (4096 + NW * 9216)

__global__ void __launch_bounds__(THREADS, 1) gnn_mma(Pm P)
{
    const int tid = threadIdx.x, lane = tid & 31, w = tid >> 5;
    float* miscf = (float*)smem;
    {
        const float* srcs[9] = {P.bp1, P.b1, P.bp2, P.b2, P.Mb1, P.Mb2, P.Mb3,
                                P.MW4, P.Mb4};
        const int offs[9] = {0, 64, 128, 192, 256, 384, 512, 640, 896};
        const int lens[9] = {64, 64, 64, 64, 128, 128, 128, 256, 4};
        for (int s = 0; s < 9; s++)
            for (int i = tid; i < lens[s]; i += THREADS)
                miscf[offs[s] + i] = srcs[s][i];
    }
    __syncthreads();

    const uint32_t sb = smem_u32(smem);
    const uint32_t WB  = sb + 4096 + w * 9216;
    const uint32_t AH0 = WB, AL0 = WB + 2304, AH1 = WB + 4608, AL1 = WB + 6912;
    const int q = (lane & 3) * 2;
    const int nwarp = gridDim.x * NW;

    for (int ch = blockIdx.x * NW + w; ch < CHUNKS; ch += nwarp) {
        const int gbase = ch * 16;
        const float* obsb = P.obs + (size_t)gbase * 384;
        float Nacc[32], nn1[32], hsum[32], acc[32];

        // ---- pass 1: N1 = max_a relu(obs_a @ Wp1 + bp1) ----
        #pragma unroll
        for (int i = 0; i < 32; i++) Nacc[i] = 0.f;
        for (int a = 0; a < 6; a++) {
            __syncwarp();
            stage_obs(AH0, AL0, obsb + a * 64, lane);
            __syncwarp();
            gemm8(acc, AH0, AL0, g_frag + 0 * 4096, lane, true);      // Wp1
            #pragma unroll
            for (int j = 0; j < 8; j++) {
                float2 b = *(const float2*)(miscf + 0 + j * 8 + q);   // bp1
                Nacc[j*4+0] = fmaxf(Nacc[j*4+0], acc[j*4+0] + b.x);
                Nacc[j*4+1] = fmaxf(Nacc[j*4+1], acc[j*4+1] + b.y);
                Nacc[j*4+2] = fmaxf(Nacc[j*4+2], acc[j*4+2] + b.x);
                Nacc[j*4+3] = fmaxf(Nacc[j*4+3], acc[j*4+3] + b.y);
            }
        }
        __syncwarp();
        stageD(AH0, AL0, Nacc, lane);
        __syncwarp();
        gemm8(acc, AH0, AL0, g_frag + 2 * 4096, lane, true);          // Wn1
        #pragma unroll
        for (int j = 0; j < 8; j++) {
            float2 b = *(const float2*)(miscf + 64 + j * 8 + q);      // b1
            nn1[j*4+0] = acc[j*4+0] + b.x;
            nn1[j*4+1] = acc[j*4+1] + b.y;
            nn1[j*4+2] = acc[j*4+2] + b.x;
            nn1[j*4+3] = acc[j*4+3] + b.y;
        }

        // ---- pass 2: h_a = tanh(obs_a@Ws1 + nn1); hsum; N2 over h_a@Wp2 ----
        #pragma unroll
        for (int i = 0; i < 32; i++) { hsum[i] = 0.f; Nacc[i] = 0.f; }
        for (int a = 0; a < 6; a++) {
            __syncwarp();
            stage_obs(AH0, AL0, obsb + a * 64, lane);
            __syncwarp();
            gemm8(acc, AH0, AL0, g_frag + 1 * 4096, lane, true);      // Ws1
            #pragma unroll
            for (int i = 0; i < 32; i++) {
                float h = tanhf(acc[i] + nn1[i]);
                hsum[i] += h; acc[i] = h;
            }
            __syncwarp();
            stageD(AH0, AL0, acc, lane);
            __syncwarp();
            gemm8(acc, AH0, AL0, g_frag + 3 * 4096, lane, true);      // Wp2
            #pragma unroll
            for (int j = 0; j < 8; j++) {
                float2 b = *(const float2*)(miscf + 128 + j * 8 + q); // bp2
                Nacc[j*4+0] = fmaxf(Nacc[j*4+0], acc[j*4+0] + b.x);
                Nacc[j*4+1] = fmaxf(Nacc[j*4+1], acc[j*4+1] + b.y);
                Nacc[j*4+2] = fmaxf(Nacc[j*4+2], acc[j*4+2] + b.x);
                Nacc[j*4+3] = fmaxf(Nacc[j*4+3], acc[j*4+3] + b.y);
            }
        }
        // ---- RES = (hsum/6)@Ws2 + N2@Wn2 + b2 ----
        __syncwarp();
        stageD(AH0, AL0, Nacc, lane);
        __syncwarp();
        gemm8(acc, AH0, AL0, g_frag + 5 * 4096, lane, true);          // Wn2
        #pragma unroll
        for (int i = 0; i < 32; i++) hsum[i] *= (1.f / 6.f);
        __syncwarp();
        stageD(AH0, AL0, hsum, lane);
        __syncwarp();
        gemm8(acc, AH0, AL0, g_frag + 4 * 4096, lane, false);         // +Ws2
        #pragma unroll
        for (int j = 0; j < 8; j++) {
            float2 b = *(const float2*)(miscf + 192 + j * 8 + q);     // b2
            hsum[j*4+0] = acc[j*4+0] + b.x;   // hsum now holds RES
            hsum[j*4+1] = acc[j*4+1] + b.y;
            hsum[j*4+2] = acc[j*4+2] + b.x;
            hsum[j*4+3] = acc[j*4+3] + b.y;
        }
        __syncwarp();
        stageD(AH1, AL1, hsum, lane);                                 // RES -> slot1
        __syncwarp();

        // ---- per-type MLP + head ----
        float t0r0 = 0.f, t0r1 = 0.f, t0r2 = 0.f, t0r3 = 0.f;
        #pragma unroll
        for (int t = 0; t < 2; t++) {
            gemm8(acc, AH1, AL1, g_frag + (6 + t) * 4096, lane, true);   // MW1t
            #pragma unroll
            for (int j = 0; j < 8; j++) {
                float2 b = *(const float2*)(miscf + 256 + t * 64 + j * 8 + q);
                acc[j*4+0] = fmaxf(acc[j*4+0] + b.x, 0.f);
                acc[j*4+1] = fmaxf(acc[j*4+1] + b.y, 0.f);
                acc[j*4+2] = fmaxf(acc[j*4+2] + b.x, 0.f);
                acc[j*4+3] = fmaxf(acc[j*4+3] + b.y, 0.f);
            }
            __syncwarp();
            stageD(AH0, AL0, acc, lane);
            __syncwarp();
            gemm8(acc, AH0, AL0, g_frag + (8 + t) * 4096, lane, true);   // MW2t
            #pragma unroll
            for (int j = 0; j < 8; j++) {
                float2 b = *(const float2*)(miscf + 384 + t * 64 + j * 8 + q);
                acc[j*4+0] = fmaxf(acc[j*4+0] + b.x, 0.f);
                acc[j*4+1] = fmaxf(acc[j*4+1] + b.y, 0.f);
                acc[j*4+2] = fmaxf(acc[j*4+2] + b.x, 0.f);
                acc[j*4+3] = fmaxf(acc[j*4+3] + b.y, 0.f);
            }
            __syncwarp();
            stageD(AH0, AL0, acc, lane);
            __syncwarp();
            gemm8(acc, AH0, AL0, g_frag + (10 + t) * 4096, lane, true);  // MW3t
            float s0a = 0.f, s1a = 0.f, s0b = 0.f, s1b = 0.f;
            #pragma unroll
            for (int j = 0; j < 8; j++) {
                float2 b = *(const float2*)(miscf + 512 + t * 64 + j * 8 + q);
                float x0 = fmaxf(acc[j*4+0] + b.x, 0.f);
                float x1 = fmaxf(acc[j*4+1] + b.y, 0.f);
                float x2 = fmaxf(acc[j*4+2] + b.x, 0.f);
                float x3 = fmaxf(acc[j*4+3] + b.y, 0.f);
                float4 w4 = *(const float4*)(miscf + 640 + t * 128 + (j * 8 + q) * 2);
                s0a += x0 * w4.x + x1 * w4.z;
                s1a += x0 * w4.y + x1 * w4.w;
                s0b += x2 * w4.x + x3 * w4.z;
                s1b += x2 * w4.y + x3 * w4.w;
            }
            #pragma unroll
            for (int off = 1; off <= 2; off <<= 1) {
                s0a += __shfl_xor_sync(0xffffffffu, s0a, off);
                s1a += __shfl_xor_sync(0xffffffffu, s1a, off);
                s0b += __shfl_xor_sync(0xffffffffu, s0b, off);
                s1b += __shfl_xor_sync(0xffffffffu, s1b, off);
            }
            float m0 = miscf[896 + t * 2], m1 = miscf[897 + t * 2];
            s0a = tanhf(s0a + m0); s1a = tanhf(s1a + m1);
            s0b = tanhf(s0b + m0); s1b = tanhf(s1b + m1);
            if (t == 0) { t0r0 = s0a; t0r1 = s1a; t0r2 = s0b; t0r3 = s1b; }
            else if ((lane & 3) == 0) {
                int r = lane >> 2;
                float4* d0 = (float4*)(P.out + (size_t)(gbase + r) * 12);
                d0[0] = make_float4(t0r0, t0r1, t0r0, t0r1);
                d0[1] = make_float4(t0r0, t0r1, t0r0, t0r1);
                d0[2] = make_float4(t0r0, t0r1, s0a, s1a);
                float4* d1 = (float4*)(P.out + (size_t)(gbase + r + 8) * 12);
                d1[0] = make_float4(t0r2, t0r3, t0r2, t0r3);
                d1[1] = make_float4(t0r2, t0r3, t0r2, t0r3);
                d1[2] = make_float4(t0r2, t0r3, s0b, s1b);
            }
            __syncwarp();
        }
    }
}

extern "C" void kernel_launch(void* const* d_in, const int* in_sizes, int n_in,
                              void* d_out, int out_size)
{
    (void)in_sizes; (void)n_in; (void)out_size;
    const float* obs = (const float*)d_in[0];
    const float* Wp1 = (const float*)d_in[1];  const float* bp1 = (const float*)d_in[2];
    const float* Ws1 = (const float*)d_in[3];  const float* Wn1 = (const float*)d_in[4];
    const float* b1  = (const float*)d_in[5];
    const float* Wp2 = (const float*)d_in[6];  const float* bp2 = (const float*)d_in[7];
    const float* Ws2 = (const float*)d_in[8];  const float* Wn2 = (const float*)d_in[9];
    const float* b2  = (const float*)d_in[10];
    const float* MW1 = (const float*)d_in[11]; const float* Mb1 = (const float*)d_in[12];
    const float* MW2 = (const float*)d_in[13]; const float* Mb2 = (const float*)d_in[14];
    const float* MW3 = (const float*)d_in[15]; const float* Mb3 = (const float*)d_in[16];
    const float* MW4 = (const float*)d_in[17]; const float* Mb4 = (const float*)d_in[18];

    prep_frag<<<(12 * 4096 + 255) / 256, 256>>>(Wp1, Ws1, Wn1, Wp2, Ws2, Wn2,
                                                MW1, MW2, MW3);

    Pm P;
    P.obs = obs; P.bp1 = bp1; P.b1 = b1; P.bp2 = bp2; P.b2 = b2;
    P.Mb1 = Mb1; P.Mb2 = Mb2; P.Mb3 = Mb3; P.MW4 = MW4; P.Mb4 = Mb4;
    P.out = (float*)d_out;

    int dev = 0, nsm = 148;
    cudaGetDevice(&dev);
    cudaDeviceGetAttribute(&nsm, cudaDevAttrMultiProcessorCount, dev);

    cudaFuncSetAttribute(gnn_mma, cudaFuncAttributeMaxDynamicSharedMemorySize,
                         SMEM_TOTAL);
    gnn_mma<<<nsm, THREADS, SMEM_TOTAL>>>(P);
}